// round 13
// baseline (speedup 1.0000x reference)
#include <cuda_runtime.h>
#include <cuda_fp16.h>
#include <cstdint>
#include <math.h>

#define NB 16
#define NP 1024
#define CF 768
#define CC 512
#define HW 28
#define PIX 784
#define KT 32
#define STR 40
#define STAGES 4
#define BUF_ELE (128 * STR)
#define SMEM_BYTES (STAGES * 2 * BUF_ELE * 2)   // 81920 B per CTA
#define NCH 40

// ======================= scratch (device globals) =======================
__device__ __half g_Ftb [NB * PIX * CF];
__device__ __half g_Fptb[NB * PIX * CF];
__device__ __half g_Ctb [NB * PIX * CC];
__device__ __half g_Cptb[NB * PIX * CC];

__device__ __half g_F1 [NB * NP * CF];
__device__ __half g_C1 [NB * NP * CC];
__device__ __half g_F2p[NB * NP * CF];
__device__ __half g_C2p[NB * NP * CC];
__device__ __half g_Fn0[NB * NP * CF];
__device__ __half g_Cn0[NB * NP * CC];
__device__ __half g_Fn1[NB * NP * CF];
__device__ __half g_Cn1[NB * NP * CC];

__device__ float  g_rowfd[4 * NB * NP];
__device__ float  g_rowrc[4 * NB * NP];
__device__ double g_scal[4];
__device__ double g_acc[4][3];

__device__ __forceinline__ uint32_t smem_u32(const void* p) {
    uint32_t a;
    asm("{ .reg .u64 t; cvta.to.shared.u64 t, %1; cvt.u32.u64 %0, t; }" : "=r"(a) : "l"(p));
    return a;
}
#define LDSM_X4(r0, r1, r2, r3, addr) \
    asm volatile("ldmatrix.sync.aligned.m8n8.x4.shared.b16 {%0,%1,%2,%3}, [%4];" \
                 : "=r"(r0), "=r"(r1), "=r"(r2), "=r"(r3) : "r"(addr))
#define CP_ASYNC_16(dst, src) \
    asm volatile("cp.async.cg.shared.global [%0], [%1], 16;" :: "r"(dst), "l"(src))
#define CP_COMMIT() asm volatile("cp.async.commit_group;" ::: "memory")
#define CP_WAIT2()  asm volatile("cp.async.wait_group 2;" ::: "memory")

// ======================= transpose-all + zero fold =======================
__global__ void __launch_bounds__(256) transpose_all_kernel(
    const float* __restrict__ f, const float* __restrict__ fp,
    const float* __restrict__ c, const float* __restrict__ cp)
{
    int tensor = blockIdx.y;
    int bx = blockIdx.x;
    int tid = threadIdx.y * 32 + threadIdx.x;

    if (tensor == 0 && bx < 256) {
        int idx = bx * 256 + tid;
        g_rowfd[idx] = 0.f;
        g_rowrc[idx] = 0.f;
        if (idx < 4)  g_scal[idx] = 0.0;
        if (idx < 12) g_acc[idx / 3][idx % 3] = 0.0;
    }

    const float* in;
    __half* out;
    int C;
    switch (tensor) {
        case 0:  in = f;  out = g_Ftb;  C = CF; break;
        case 1:  in = fp; out = g_Fptb; C = CF; break;
        case 2:  in = c;  out = g_Ctb;  C = CC; break;
        default: in = cp; out = g_Cptb; C = CC; break;
    }
    int h0   = (bx % 25) * 32;
    int rest = bx / 25;
    int cidx = rest % 12;
    int b    = rest / 12;
    if (cidx * 64 >= C) return;
    int c0 = cidx * 64;

    __shared__ float t[64][33];
    int x = threadIdx.x, y = threadIdx.y;
    #pragma unroll
    for (int i = 0; i < 64; i += 8) {
        int cc = c0 + y + i, h = h0 + x;
        if (h < PIX) t[y + i][x] = in[((size_t)b * C + cc) * PIX + h];
    }
    __syncthreads();
    #pragma unroll
    for (int i = 0; i < 32; i += 8) {
        int h = h0 + y + i;
        if (h < PIX) {
            __half2 v = __floats2half2_rn(t[2 * x][y + i], t[2 * x + 1][y + i]);
            *(__half2*)(out + ((size_t)b * PIX + h) * C + c0 + 2 * x) = v;
        }
    }
}

// ======================= fused bilinear sample + normalize (R9 shape) =======================
__global__ void __launch_bounds__(160) sample_all_kernel(
    const float* __restrict__ coords1,
    const float* __restrict__ coords2,
    const int*   __restrict__ perms)
{
    int bp = blockIdx.x;
    int g  = blockIdx.y;
    int b = bp >> 10, p = bp & 1023;

    const float* coords = (g == 0) ? coords1 : coords2;
    int bs = b;
    if (g == 2) bs = perms[b];
    else if (g == 3) bs = perms[NB + b];

    const __half *srcF, *srcC;
    __half *dstF, *dstC;
    switch (g) {
        case 0:  srcF = g_Ftb;  srcC = g_Ctb;  dstF = g_F1;  dstC = g_C1;  break;
        case 1:  srcF = g_Fptb; srcC = g_Cptb; dstF = g_F2p; dstC = g_C2p; break;
        case 2:  srcF = g_Ftb;  srcC = g_Ctb;  dstF = g_Fn0; dstC = g_Cn0; break;
        default: srcF = g_Ftb;  srcC = g_Ctb;  dstF = g_Fn1; dstC = g_Cn1; break;
    }

    float u = coords[(size_t)(b * NP + p) * 2 + 0];
    float v = coords[(size_t)(b * NP + p) * 2 + 1];
    float x = ((u * 2.f - 1.f) + 1.f) * 0.5f * (float)(HW - 1);
    float y = ((v * 2.f - 1.f) + 1.f) * 0.5f * (float)(HW - 1);
    float x0 = floorf(x), y0 = floorf(y);
    float wx = x - x0, wy = y - y0;
    int x0c = (int)fminf(fmaxf(x0,       0.f), (float)(HW - 1));
    int x1c = (int)fminf(fmaxf(x0 + 1.f, 0.f), (float)(HW - 1));
    int y0c = (int)fminf(fmaxf(y0,       0.f), (float)(HW - 1));
    int y1c = (int)fminf(fmaxf(y0 + 1.f, 0.f), (float)(HW - 1));
    float w00 = (1.f - wx) * (1.f - wy);
    float w01 = (1.f - wx) * wy;
    float w10 = wx * (1.f - wy);
    float w11 = wx * wy;
    int o00 = y0c * HW + x0c, o01 = y1c * HW + x0c;
    int o10 = y0c * HW + x1c, o11 = y1c * HW + x1c;

    int tid = threadIdx.x;
    bool isF = tid < 96;
    const __half* S = isF ? srcF : srcC;
    int C  = isF ? CF : CC;
    int vx = isF ? tid : tid - 96;

    size_t rb = (size_t)bs * PIX;
    uint4 q00 = *(const uint4*)(S + (rb + o00) * C + vx * 8);
    uint4 q01 = *(const uint4*)(S + (rb + o01) * C + vx * 8);
    uint4 q10 = *(const uint4*)(S + (rb + o10) * C + vx * 8);
    uint4 q11 = *(const uint4*)(S + (rb + o11) * C + vx * 8);

    float2 vv[4] = {{0.f,0.f},{0.f,0.f},{0.f,0.f},{0.f,0.f}};
    auto addc = [&](uint4 q, float w) {
        uint32_t arr[4] = {q.x, q.y, q.z, q.w};
        #pragma unroll
        for (int k = 0; k < 4; k++) {
            float2 fv = __half22float2(*(__half2*)&arr[k]);
            vv[k].x += w * fv.x;
            vv[k].y += w * fv.y;
        }
    };
    addc(q00, w00); addc(q01, w01); addc(q10, w10); addc(q11, w11);

    float ssq = 0.f;
    #pragma unroll
    for (int k = 0; k < 4; k++) ssq += vv[k].x * vv[k].x + vv[k].y * vv[k].y;

    #pragma unroll
    for (int off = 16; off; off >>= 1) ssq += __shfl_xor_sync(0xffffffffu, ssq, off);
    __shared__ float sred[5];
    if ((tid & 31) == 0) sred[tid >> 5] = ssq;
    __syncthreads();
    float sum = isF ? (sred[0] + sred[1] + sred[2]) : (sred[3] + sred[4]);
    float scale = 1.f / fmaxf(sqrtf(sum), 1e-10f);

    uint4 o;
    uint32_t* op = (uint32_t*)&o;
    #pragma unroll
    for (int k = 0; k < 4; k++) {
        __half2 h = __floats2half2_rn(vv[k].x * scale, vv[k].y * scale);
        op[k] = *(uint32_t*)&h;
    }
    __half* D = isF ? dstF : dstC;
    *(uint4*)(D + (size_t)(b * NP + p) * C + vx * 8) = o;
}

// ======================= HMMA correlation (fp16 accumulate: 2x rate) =======================
__device__ __forceinline__ void mma_f16(uint32_t (&d)[2], const uint32_t (&a)[4],
                                        uint32_t b0, uint32_t b1) {
    asm volatile(
        "mma.sync.aligned.m16n8k16.row.col.f16.f16.f16.f16 "
        "{%0,%1}, {%2,%3,%4,%5}, {%6,%7}, {%0,%1};\n"
        : "+r"(d[0]), "+r"(d[1])
        : "r"(a[0]), "r"(a[1]), "r"(a[2]), "r"(a[3]), "r"(b0), "r"(b1));
}

__device__ __forceinline__ void warp_mma_tile_ldsm(
    uint32_t smA, uint32_t smB, uint32_t aoff, uint32_t boff, uint32_t (&acc)[2][4][2])
{
    #pragma unroll
    for (int ks = 0; ks < 2; ks++) {
        uint32_t a[2][4];
        #pragma unroll
        for (int i = 0; i < 2; i++) {
            uint32_t addr = smA + 2u * (aoff + i * 16 * STR + ks * 16);
            LDSM_X4(a[i][0], a[i][1], a[i][2], a[i][3], addr);
        }
        #pragma unroll
        for (int jp = 0; jp < 2; jp++) {
            uint32_t baddr = smB + 2u * (boff + jp * 16 * STR + ks * 16);
            uint32_t b0, b1, b2, b3;
            LDSM_X4(b0, b1, b2, b3, baddr);
            #pragma unroll
            for (int i = 0; i < 2; i++) {
                mma_f16(acc[i][jp * 2 + 0], a[i], b0, b1);
                mma_f16(acc[i][jp * 2 + 1], a[i], b2, b3);
            }
        }
    }
}

template <bool SYM>
__device__ __forceinline__ void corr_body(
    int slot, int b, int p0, int q0,
    const __half* Af_r, const __half* Ac_r,
    const __half* Bf_r, const __half* Bc_r)
{
    extern __shared__ __align__(16) __half dynbuf[];
    __shared__ float  red_f[128];
    __shared__ float  red_r[128];
    __shared__ float  red_cf[128];
    __shared__ float  red_cr[128];
    __shared__ double red_d[16];

    int tid = threadIdx.x;
    int wid = tid >> 5, lane = tid & 31;
    int g = lane >> 2, t = lane & 3;
    int wm = wid >> 2, wn = wid & 3;
    int lrow = tid >> 2, lseg = tid & 3;

    uint32_t smem_base = smem_u32(dynbuf);
    uint32_t aoff = (uint32_t)((wm * 32 + (lane & 15)) * STR + (lane >> 4) * 8);
    uint32_t boff = (uint32_t)((wn * 32 + ((lane >> 4) & 1) * 8 + (lane & 7)) * STR + ((lane >> 3) & 1) * 8);
    uint32_t stoff = (uint32_t)(lrow * STR + lseg * 8) * 2u;

    if (tid < 128) {
        red_f[tid] = 0.f; red_r[tid] = 0.f;
        if (SYM) { red_cf[tid] = 0.f; red_cr[tid] = 0.f; }
    }

    uint32_t facc[2][4][2] = {};
    uint32_t cacc[2][4][2] = {};

    auto issue_load = [&](int c) {
        int s = c & (STAGES - 1);
        uint32_t da = smem_base + (uint32_t)((s * 2 + 0) * BUF_ELE) * 2u + stoff;
        uint32_t db = smem_base + (uint32_t)((s * 2 + 1) * BUF_ELE) * 2u + stoff;
        const __half *pa, *pb;
        if (c < 24) {
            size_t off = (size_t)lrow * CF + c * KT + lseg * 8;
            pa = Af_r + off;  pb = Bf_r + off;
        } else {
            size_t off = (size_t)lrow * CC + (c - 24) * KT + lseg * 8;
            pa = Ac_r + off;  pb = Bc_r + off;
        }
        CP_ASYNC_16(da, pa);
        CP_ASYNC_16(db, pb);
        CP_COMMIT();
    };

    issue_load(0);
    issue_load(1);
    issue_load(2);

    for (int c = 0; c < NCH; c++) {
        CP_WAIT2();
        __syncthreads();
        if (c + 3 < NCH) issue_load(c + 3);
        int s = c & (STAGES - 1);
        uint32_t sa = smem_base + (uint32_t)((s * 2 + 0) * BUF_ELE) * 2u;
        uint32_t sb = smem_base + (uint32_t)((s * 2 + 1) * BUF_ELE) * 2u;
        if (c < 24) warp_mma_tile_ldsm(sa, sb, aoff, boff, facc);
        else        warp_mma_tile_ldsm(sa, sb, aoff, boff, cacc);
    }

    // -------- epilogue (unpack fp16 accums to fp32) --------
    float lsum = 0.f;
    float rf[2][2] = {}, rr[2][2] = {};
    float cf0[4] = {}, cf1[4] = {}, cr0[4] = {}, cr1[4] = {};
    #pragma unroll
    for (int i = 0; i < 2; i++) {
        #pragma unroll
        for (int j = 0; j < 4; j++) {
            float2 fl0 = __half22float2(*(__half2*)&facc[i][j][0]);
            float2 fl1 = __half22float2(*(__half2*)&facc[i][j][1]);
            float2 cl0 = __half22float2(*(__half2*)&cacc[i][j][0]);
            float2 cl1 = __half22float2(*(__half2*)&cacc[i][j][1]);
            float f0 = fl0.x, f1 = fl0.y, f2 = fl1.x, f3 = fl1.y;
            float r0 = fmaxf(cl0.x, 0.f), r1 = fmaxf(cl0.y, 0.f);
            float r2 = fmaxf(cl1.x, 0.f), r3 = fmaxf(cl1.y, 0.f);
            rf[i][0] += f0 + f1;  rf[i][1] += f2 + f3;
            rr[i][0] += r0 + r1;  rr[i][1] += r2 + r3;
            if (SYM) {
                cf0[j] += f0 + f2;  cf1[j] += f1 + f3;
                cr0[j] += r0 + r2;  cr1[j] += r1 + r3;
            }
            lsum += r0 * f0 + r1 * f1 + r2 * f2 + r3 * f3;
        }
    }
    #pragma unroll
    for (int off = 1; off < 4; off <<= 1) {
        #pragma unroll
        for (int i = 0; i < 2; i++) {
            rf[i][0] += __shfl_xor_sync(0xffffffffu, rf[i][0], off);
            rf[i][1] += __shfl_xor_sync(0xffffffffu, rf[i][1], off);
            rr[i][0] += __shfl_xor_sync(0xffffffffu, rr[i][0], off);
            rr[i][1] += __shfl_xor_sync(0xffffffffu, rr[i][1], off);
        }
    }
    if (t == 0) {
        #pragma unroll
        for (int i = 0; i < 2; i++) {
            int r0i = wm * 32 + i * 16 + g;
            atomicAdd(&red_f[r0i],     rf[i][0]);
            atomicAdd(&red_f[r0i + 8], rf[i][1]);
            atomicAdd(&red_r[r0i],     rr[i][0]);
            atomicAdd(&red_r[r0i + 8], rr[i][1]);
        }
    }
    if (SYM) {
        #pragma unroll
        for (int off = 4; off < 32; off <<= 1) {
            #pragma unroll
            for (int j = 0; j < 4; j++) {
                cf0[j] += __shfl_xor_sync(0xffffffffu, cf0[j], off);
                cf1[j] += __shfl_xor_sync(0xffffffffu, cf1[j], off);
                cr0[j] += __shfl_xor_sync(0xffffffffu, cr0[j], off);
                cr1[j] += __shfl_xor_sync(0xffffffffu, cr1[j], off);
            }
        }
        if (g == 0) {
            #pragma unroll
            for (int j = 0; j < 4; j++) {
                int c0i = wn * 32 + j * 8 + 2 * t;
                atomicAdd(&red_cf[c0i],     cf0[j]);
                atomicAdd(&red_cf[c0i + 1], cf1[j]);
                atomicAdd(&red_cr[c0i],     cr0[j]);
                atomicAdd(&red_cr[c0i + 1], cr1[j]);
            }
        }
    }
    #pragma unroll
    for (int off = 16; off; off >>= 1) lsum += __shfl_xor_sync(0xffffffffu, lsum, off);
    if (lane == 0) red_d[wid] = (double)lsum;
    __syncthreads();

    if (tid == 0) {
        double s = 0.0;
        #pragma unroll
        for (int w = 0; w < 16; w++) s += red_d[w];
        atomicAdd(&g_scal[slot], SYM ? 2.0 * s : s);
    }
    if (tid < 128) {
        int gi = slot * NB * NP + b * NP + p0 + tid;
        atomicAdd(&g_rowfd[gi], red_f[tid]);
        atomicAdd(&g_rowrc[gi], red_r[tid]);
        if (SYM) {
            int gj = slot * NB * NP + b * NP + q0 + tid;
            atomicAdd(&g_rowfd[gj], red_cf[tid]);
            atomicAdd(&g_rowrc[gj], red_cr[tid]);
        }
    }
}

__device__ const int8_t PAIR_P[36] = {0,0,0,0,0,0,0, 1,1,1,1,1,1, 2,2,2,2,2, 3,3,3,3, 4,4,4, 5,5, 6, 0,1,2,3,4,5,6,7};
__device__ const int8_t PAIR_Q[36] = {1,2,3,4,5,6,7, 2,3,4,5,6,7, 3,4,5,6,7, 4,5,6,7, 5,6,7, 6,7, 7, 0,1,2,3,4,5,6,7};

__global__ void __launch_bounds__(512, 1) corr_all_kernel()
{
    int x = blockIdx.x;
    if (x < 576) {
        int pair = x % 36;
        int b    = x / 36;
        int p0 = (int)PAIR_P[pair] * 128;
        int q0 = (int)PAIR_Q[pair] * 128;
        const __half* Af = g_F1 + (size_t)(b * NP + p0) * CF;
        const __half* Ac = g_C1 + (size_t)(b * NP + p0) * CC;
        const __half* Bf = g_F1 + (size_t)(b * NP + q0) * CF;
        const __half* Bc = g_C1 + (size_t)(b * NP + q0) * CC;
        if (pair < 28) corr_body<true >(0, b, p0, q0, Af, Ac, Bf, Bc);
        else           corr_body<false>(0, b, p0, q0, Af, Ac, Bf, Bc);
    } else {
        int j  = x - 576;
        int q0 = (j & 7) * 128;
        int p0 = ((j >> 3) & 7) * 128;
        int z  = j >> 6;
        int slot = 1 + (z >> 4);
        int b    = z & 15;
        const __half *Bf, *Bc;
        switch (slot) {
            case 1:  Bf = g_F2p; Bc = g_C2p; break;
            case 2:  Bf = g_Fn0; Bc = g_Cn0; break;
            default: Bf = g_Fn1; Bc = g_Cn1; break;
        }
        corr_body<false>(slot, b, p0, q0,
                         g_F1 + (size_t)(b * NP + p0) * CF,
                         g_C1 + (size_t)(b * NP + p0) * CC,
                         Bf   + (size_t)(b * NP + q0) * CF,
                         Bc   + (size_t)(b * NP + q0) * CC);
    }
}

// ======================= parallel reduce + tiny finalize =======================
__global__ void __launch_bounds__(256) reduce_kernel()
{
    int blk  = blockIdx.x;
    int slot = blk >> 6;
    int tid  = threadIdx.x;
    int i = (blk & 63) * 256 + tid;

    float f = g_rowfd[slot * NB * NP + i];
    float r = g_rowrc[slot * NB * NP + i];
    double tf = (double)f, tr = (double)r, cx = (double)f * (double)r;

    #pragma unroll
    for (int off = 16; off; off >>= 1) {
        tf += __shfl_xor_sync(0xffffffffu, tf, off);
        tr += __shfl_xor_sync(0xffffffffu, tr, off);
        cx += __shfl_xor_sync(0xffffffffu, cx, off);
    }
    __shared__ double sred[3][8];
    if ((tid & 31) == 0) { sred[0][tid >> 5] = tf; sred[1][tid >> 5] = tr; sred[2][tid >> 5] = cx; }
    __syncthreads();
    if (tid < 8) {
        double a = sred[0][tid], b = sred[1][tid], c = sred[2][tid];
        #pragma unroll
        for (int off = 4; off; off >>= 1) {
            a += __shfl_xor_sync(0xffu, a, off);
            b += __shfl_xor_sync(0xffu, b, off);
            c += __shfl_xor_sync(0xffu, c, off);
        }
        if (tid == 0) {
            atomicAdd(&g_acc[slot][0], a);
            atomicAdd(&g_acc[slot][1], b);
            atomicAdd(&g_acc[slot][2], c);
        }
    }
}

__global__ void final_kernel(float* out)
{
    const double BPQ = (double)NB * (double)NP * (double)NP;
    const double Q   = (double)NP;
    const double shifts[4] = {0.18, 0.12, 0.46, 0.46};
    double loss[4];
    #pragma unroll
    for (int s = 0; s < 4; s++) {
        double tf = g_acc[s][0], tr = g_acc[s][1], cx = g_acc[s][2];
        double A  = g_scal[s];
        double gm = tf / BPQ;
        loss[s] = (-A + cx / Q) / BPQ - (gm - shifts[s]) * (tr / BPQ);
    }
    out[0] = (float)loss[0];
    out[1] = (float)loss[1];
    out[2] = (float)(0.5 * (loss[2] + loss[3]));
}

// ======================= launch =======================
extern "C" void kernel_launch(void* const* d_in, const int* in_sizes, int n_in,
                              void* d_out, int out_size)
{
    const float* orig_feats     = (const float*)d_in[0];
    const float* orig_feats_pos = (const float*)d_in[1];
    const float* orig_code      = (const float*)d_in[4];
    const float* orig_code_pos  = (const float*)d_in[5];
    const float* coords1        = (const float*)d_in[8];
    const float* coords2        = (const float*)d_in[9];
    const int*   perms          = (const int*)d_in[10];
    float* out = (float*)d_out;

    cudaFuncSetAttribute(corr_all_kernel, cudaFuncAttributeMaxDynamicSharedMemorySize, SMEM_BYTES);

    dim3 tb(32, 8);
    transpose_all_kernel<<<dim3(4800, 4), tb>>>(orig_feats, orig_feats_pos,
                                                orig_code, orig_code_pos);

    sample_all_kernel<<<dim3(NB * NP, 4), 160>>>(coords1, coords2, perms);

    corr_all_kernel<<<3648, 512, SMEM_BYTES>>>();

    reduce_kernel<<<256, 256>>>();
    final_kernel<<<1, 1>>>(out);
}

// round 14
// speedup vs baseline: 1.1537x; 1.1537x over previous
#include <cuda_runtime.h>
#include <cuda_fp16.h>
#include <cstdint>
#include <math.h>

#define NB 16
#define NP 1024
#define CF 768
#define CC 512
#define HW 28
#define PIX 784
#define ROWB 80                 // padded smem row stride in BYTES (64B payload + 16B)
#define STAGES 4
#define BUF_BYTES (128 * ROWB)  // 10240 B per (stage, matrix)
#define SMEM_BYTES (STAGES * 2 * BUF_BYTES)   // 81920 B per CTA
#define NCHF 12                 // fd chunks: CF=768 fp8 bytes / 64B
#define NCH  28                 // + cd chunks: CC=512 fp16 = 1024B / 64B = 16

// ======================= scratch (device globals) =======================
__device__ __half g_Ftb [NB * PIX * CF];
__device__ __half g_Fptb[NB * PIX * CF];
__device__ __half g_Ctb [NB * PIX * CC];
__device__ __half g_Cptb[NB * PIX * CC];

// normalized feats in fp8 e4m3 (fd GEMM), code in fp16 (cd GEMM)
__device__ uint8_t g_F1 [NB * NP * CF];
__device__ __half  g_C1 [NB * NP * CC];
__device__ uint8_t g_F2p[NB * NP * CF];
__device__ __half  g_C2p[NB * NP * CC];
__device__ uint8_t g_Fn0[NB * NP * CF];
__device__ __half  g_Cn0[NB * NP * CC];
__device__ uint8_t g_Fn1[NB * NP * CF];
__device__ __half  g_Cn1[NB * NP * CC];

__device__ float  g_rowfd[4 * NB * NP];
__device__ float  g_rowrc[4 * NB * NP];
__device__ double g_scal[4];
__device__ double g_acc[4][3];

__device__ __forceinline__ uint32_t smem_u32(const void* p) {
    uint32_t a;
    asm("{ .reg .u64 t; cvta.to.shared.u64 t, %1; cvt.u32.u64 %0, t; }" : "=r"(a) : "l"(p));
    return a;
}
#define LDSM_X4(r0, r1, r2, r3, addr) \
    asm volatile("ldmatrix.sync.aligned.m8n8.x4.shared.b16 {%0,%1,%2,%3}, [%4];" \
                 : "=r"(r0), "=r"(r1), "=r"(r2), "=r"(r3) : "r"(addr))
#define CP_ASYNC_16(dst, src) \
    asm volatile("cp.async.cg.shared.global [%0], [%1], 16;" :: "r"(dst), "l"(src))
#define CP_COMMIT() asm volatile("cp.async.commit_group;" ::: "memory")
#define CP_WAIT2()  asm volatile("cp.async.wait_group 2;" ::: "memory")

// ======================= transpose-all + zero fold (all fp16) =======================
__global__ void __launch_bounds__(256) transpose_all_kernel(
    const float* __restrict__ f, const float* __restrict__ fp,
    const float* __restrict__ c, const float* __restrict__ cp)
{
    int tensor = blockIdx.y;
    int bx = blockIdx.x;
    int tid = threadIdx.y * 32 + threadIdx.x;

    if (tensor == 0 && bx < 256) {
        int idx = bx * 256 + tid;
        g_rowfd[idx] = 0.f;
        g_rowrc[idx] = 0.f;
        if (idx < 4)  g_scal[idx] = 0.0;
        if (idx < 12) g_acc[idx / 3][idx % 3] = 0.0;
    }

    const float* in;
    __half* out;
    int C;
    switch (tensor) {
        case 0:  in = f;  out = g_Ftb;  C = CF; break;
        case 1:  in = fp; out = g_Fptb; C = CF; break;
        case 2:  in = c;  out = g_Ctb;  C = CC; break;
        default: in = cp; out = g_Cptb; C = CC; break;
    }
    int h0   = (bx % 25) * 32;
    int rest = bx / 25;
    int cidx = rest % 12;
    int b    = rest / 12;
    if (cidx * 64 >= C) return;
    int c0 = cidx * 64;

    __shared__ float t[64][33];
    int x = threadIdx.x, y = threadIdx.y;
    #pragma unroll
    for (int i = 0; i < 64; i += 8) {
        int cc = c0 + y + i, h = h0 + x;
        if (h < PIX) t[y + i][x] = in[((size_t)b * C + cc) * PIX + h];
    }
    __syncthreads();
    #pragma unroll
    for (int i = 0; i < 32; i += 8) {
        int h = h0 + y + i;
        if (h < PIX) {
            __half2 v = __floats2half2_rn(t[2 * x][y + i], t[2 * x + 1][y + i]);
            *(__half2*)(out + ((size_t)b * PIX + h) * C + c0 + 2 * x) = v;
        }
    }
}

// ======================= fused bilinear sample + normalize =======================
// feats lanes (t<96) emit fp8 e4m3 (8 bytes); code lanes emit fp16 (16 bytes).
__global__ void __launch_bounds__(160) sample_all_kernel(
    const float* __restrict__ coords1,
    const float* __restrict__ coords2,
    const int*   __restrict__ perms)
{
    int bp = blockIdx.x;
    int g  = blockIdx.y;
    int b = bp >> 10, p = bp & 1023;

    const float* coords = (g == 0) ? coords1 : coords2;
    int bs = b;
    if (g == 2) bs = perms[b];
    else if (g == 3) bs = perms[NB + b];

    const __half *srcF, *srcC;
    uint8_t* dstF;
    __half*  dstC;
    switch (g) {
        case 0:  srcF = g_Ftb;  srcC = g_Ctb;  dstF = g_F1;  dstC = g_C1;  break;
        case 1:  srcF = g_Fptb; srcC = g_Cptb; dstF = g_F2p; dstC = g_C2p; break;
        case 2:  srcF = g_Ftb;  srcC = g_Ctb;  dstF = g_Fn0; dstC = g_Cn0; break;
        default: srcF = g_Ftb;  srcC = g_Ctb;  dstF = g_Fn1; dstC = g_Cn1; break;
    }

    float u = coords[(size_t)(b * NP + p) * 2 + 0];
    float v = coords[(size_t)(b * NP + p) * 2 + 1];
    float x = ((u * 2.f - 1.f) + 1.f) * 0.5f * (float)(HW - 1);
    float y = ((v * 2.f - 1.f) + 1.f) * 0.5f * (float)(HW - 1);
    float x0 = floorf(x), y0 = floorf(y);
    float wx = x - x0, wy = y - y0;
    int x0c = (int)fminf(fmaxf(x0,       0.f), (float)(HW - 1));
    int x1c = (int)fminf(fmaxf(x0 + 1.f, 0.f), (float)(HW - 1));
    int y0c = (int)fminf(fmaxf(y0,       0.f), (float)(HW - 1));
    int y1c = (int)fminf(fmaxf(y0 + 1.f, 0.f), (float)(HW - 1));
    float w00 = (1.f - wx) * (1.f - wy);
    float w01 = (1.f - wx) * wy;
    float w10 = wx * (1.f - wy);
    float w11 = wx * wy;
    int o00 = y0c * HW + x0c, o01 = y1c * HW + x0c;
    int o10 = y0c * HW + x1c, o11 = y1c * HW + x1c;

    int tid = threadIdx.x;
    bool isF = tid < 96;
    const __half* S = isF ? srcF : srcC;
    int C  = isF ? CF : CC;
    int vx = isF ? tid : tid - 96;

    size_t rb = (size_t)bs * PIX;
    uint4 q00 = *(const uint4*)(S + (rb + o00) * C + vx * 8);
    uint4 q01 = *(const uint4*)(S + (rb + o01) * C + vx * 8);
    uint4 q10 = *(const uint4*)(S + (rb + o10) * C + vx * 8);
    uint4 q11 = *(const uint4*)(S + (rb + o11) * C + vx * 8);

    float2 vv[4] = {{0.f,0.f},{0.f,0.f},{0.f,0.f},{0.f,0.f}};
    auto addc = [&](uint4 q, float w) {
        uint32_t arr[4] = {q.x, q.y, q.z, q.w};
        #pragma unroll
        for (int k = 0; k < 4; k++) {
            float2 fv = __half22float2(*(__half2*)&arr[k]);
            vv[k].x += w * fv.x;
            vv[k].y += w * fv.y;
        }
    };
    addc(q00, w00); addc(q01, w01); addc(q10, w10); addc(q11, w11);

    float ssq = 0.f;
    #pragma unroll
    for (int k = 0; k < 4; k++) ssq += vv[k].x * vv[k].x + vv[k].y * vv[k].y;

    #pragma unroll
    for (int off = 16; off; off >>= 1) ssq += __shfl_xor_sync(0xffffffffu, ssq, off);
    __shared__ float sred[5];
    if ((tid & 31) == 0) sred[tid >> 5] = ssq;
    __syncthreads();
    float sum = isF ? (sred[0] + sred[1] + sred[2]) : (sred[3] + sred[4]);
    float scale = 1.f / fmaxf(sqrtf(sum), 1e-10f);

    if (isF) {
        // pack 8 normalized floats -> 8 fp8 e4m3 bytes (cvt packs arg0 into HIGH byte)
        uint16_t h[4];
        #pragma unroll
        for (int k = 0; k < 4; k++) {
            asm("cvt.rn.satfinite.e4m3x2.f32 %0, %1, %2;"
                : "=h"(h[k]) : "f"(vv[k].y * scale), "f"(vv[k].x * scale));
        }
        uint2 o;
        o.x = (uint32_t)h[0] | ((uint32_t)h[1] << 16);
        o.y = (uint32_t)h[2] | ((uint32_t)h[3] << 16);
        *(uint2*)(dstF + (size_t)(b * NP + p) * CF + vx * 8) = o;
    } else {
        uint4 o;
        uint32_t* op = (uint32_t*)&o;
        #pragma unroll
        for (int k = 0; k < 4; k++) {
            __half2 hh = __floats2half2_rn(vv[k].x * scale, vv[k].y * scale);
            op[k] = *(uint32_t*)&hh;
        }
        *(uint4*)(dstC + (size_t)(b * NP + p) * CC + vx * 8) = o;
    }
}

// ======================= HMMA correlation: fp8 fd + fp16 cd =======================
__device__ __forceinline__ void mma_e4m3(float (&d)[4], const uint32_t (&a)[4],
                                         uint32_t b0, uint32_t b1) {
    asm volatile(
        "mma.sync.aligned.m16n8k32.row.col.f32.e4m3.e4m3.f32 "
        "{%0,%1,%2,%3}, {%4,%5,%6,%7}, {%8,%9}, {%0,%1,%2,%3};\n"
        : "+f"(d[0]), "+f"(d[1]), "+f"(d[2]), "+f"(d[3])
        : "r"(a[0]), "r"(a[1]), "r"(a[2]), "r"(a[3]), "r"(b0), "r"(b1));
}
__device__ __forceinline__ void mma_f16(uint32_t (&d)[2], const uint32_t (&a)[4],
                                        uint32_t b0, uint32_t b1) {
    asm volatile(
        "mma.sync.aligned.m16n8k16.row.col.f16.f16.f16.f16 "
        "{%0,%1}, {%2,%3,%4,%5}, {%6,%7}, {%0,%1};\n"
        : "+r"(d[0]), "+r"(d[1])
        : "r"(a[0]), "r"(a[1]), "r"(a[2]), "r"(a[3]), "r"(b0), "r"(b1));
}

// All offsets in BYTES. Per 64B-payload chunk: 2 ks-steps of 32B.
// fp8 (k32) and fp16 (k16) share the same byte-identical fragment layout.
__device__ __forceinline__ void tile_fp8(
    uint32_t smA, uint32_t smB, uint32_t aoffB, uint32_t boffB, float (&acc)[2][4][4])
{
    #pragma unroll
    for (int ks = 0; ks < 2; ks++) {
        uint32_t a[2][4];
        #pragma unroll
        for (int i = 0; i < 2; i++) {
            LDSM_X4(a[i][0], a[i][1], a[i][2], a[i][3],
                    smA + aoffB + i * 16 * ROWB + ks * 32);
        }
        #pragma unroll
        for (int jp = 0; jp < 2; jp++) {
            uint32_t b0, b1, b2, b3;
            LDSM_X4(b0, b1, b2, b3, smB + boffB + jp * 16 * ROWB + ks * 32);
            #pragma unroll
            for (int i = 0; i < 2; i++) {
                mma_e4m3(acc[i][jp * 2 + 0], a[i], b0, b1);
                mma_e4m3(acc[i][jp * 2 + 1], a[i], b2, b3);
            }
        }
    }
}
__device__ __forceinline__ void tile_fp16(
    uint32_t smA, uint32_t smB, uint32_t aoffB, uint32_t boffB, uint32_t (&acc)[2][4][2])
{
    #pragma unroll
    for (int ks = 0; ks < 2; ks++) {
        uint32_t a[2][4];
        #pragma unroll
        for (int i = 0; i < 2; i++) {
            LDSM_X4(a[i][0], a[i][1], a[i][2], a[i][3],
                    smA + aoffB + i * 16 * ROWB + ks * 32);
        }
        #pragma unroll
        for (int jp = 0; jp < 2; jp++) {
            uint32_t b0, b1, b2, b3;
            LDSM_X4(b0, b1, b2, b3, smB + boffB + jp * 16 * ROWB + ks * 32);
            #pragma unroll
            for (int i = 0; i < 2; i++) {
                mma_f16(acc[i][jp * 2 + 0], a[i], b0, b1);
                mma_f16(acc[i][jp * 2 + 1], a[i], b2, b3);
            }
        }
    }
}

template <bool SYM>
__device__ __forceinline__ void corr_body(
    int slot, int b, int p0, int q0,
    const uint8_t* Af_r, const __half* Ac_r,
    const uint8_t* Bf_r, const __half* Bc_r)
{
    extern __shared__ __align__(16) uint8_t dynbuf[];
    __shared__ float  red_f[128];
    __shared__ float  red_r[128];
    __shared__ float  red_cf[128];
    __shared__ float  red_cr[128];
    __shared__ double red_d[16];

    int tid = threadIdx.x;
    int wid = tid >> 5, lane = tid & 31;
    int g = lane >> 2, t = lane & 3;
    int wm = wid >> 2, wn = wid & 3;
    int lrow = tid >> 2, lseg = tid & 3;

    uint32_t smem_base = smem_u32(dynbuf);
    uint32_t aoffB = (uint32_t)((wm * 32 + (lane & 15)) * ROWB + (lane >> 4) * 16);
    uint32_t boffB = (uint32_t)((wn * 32 + ((lane >> 4) & 1) * 8 + (lane & 7)) * ROWB + ((lane >> 3) & 1) * 16);
    uint32_t stoff = (uint32_t)(lrow * ROWB + lseg * 16);

    if (tid < 128) {
        red_f[tid] = 0.f; red_r[tid] = 0.f;
        if (SYM) { red_cf[tid] = 0.f; red_cr[tid] = 0.f; }
    }

    float    facc[2][4][4] = {};
    uint32_t cacc[2][4][2] = {};

    const uint8_t* AcB = (const uint8_t*)Ac_r;
    const uint8_t* BcB = (const uint8_t*)Bc_r;

    auto issue_load = [&](int c) {
        int s = c & (STAGES - 1);
        uint32_t da = smem_base + (uint32_t)((s * 2 + 0) * BUF_BYTES) + stoff;
        uint32_t db = smem_base + (uint32_t)((s * 2 + 1) * BUF_BYTES) + stoff;
        const uint8_t *pa, *pb;
        if (c < NCHF) {
            size_t off = (size_t)lrow * CF + c * 64 + lseg * 16;
            pa = Af_r + off;  pb = Bf_r + off;
        } else {
            size_t off = (size_t)lrow * (CC * 2) + (c - NCHF) * 64 + lseg * 16;
            pa = AcB + off;   pb = BcB + off;
        }
        CP_ASYNC_16(da, pa);
        CP_ASYNC_16(db, pb);
        CP_COMMIT();
    };

    issue_load(0);
    issue_load(1);
    issue_load(2);

    for (int c = 0; c < NCH; c++) {
        CP_WAIT2();
        __syncthreads();
        if (c + 3 < NCH) issue_load(c + 3);
        int s = c & (STAGES - 1);
        uint32_t sa = smem_base + (uint32_t)((s * 2 + 0) * BUF_BYTES);
        uint32_t sb = smem_base + (uint32_t)((s * 2 + 1) * BUF_BYTES);
        if (c < NCHF) tile_fp8 (sa, sb, aoffB, boffB, facc);
        else          tile_fp16(sa, sb, aoffB, boffB, cacc);
    }

    // -------- epilogue --------
    float lsum = 0.f;
    float rf[2][2] = {}, rr[2][2] = {};
    float cf0[4] = {}, cf1[4] = {}, cr0[4] = {}, cr1[4] = {};
    #pragma unroll
    for (int i = 0; i < 2; i++) {
        #pragma unroll
        for (int j = 0; j < 4; j++) {
            float f0 = facc[i][j][0], f1 = facc[i][j][1];
            float f2 = facc[i][j][2], f3 = facc[i][j][3];
            float2 cl0 = __half22float2(*(__half2*)&cacc[i][j][0]);
            float2 cl1 = __half22float2(*(__half2*)&cacc[i][j][1]);
            float r0 = fmaxf(cl0.x, 0.f), r1 = fmaxf(cl0.y, 0.f);
            float r2 = fmaxf(cl1.x, 0.f), r3 = fmaxf(cl1.y, 0.f);
            rf[i][0] += f0 + f1;  rf[i][1] += f2 + f3;
            rr[i][0] += r0 + r1;  rr[i][1] += r2 + r3;
            if (SYM) {
                cf0[j] += f0 + f2;  cf1[j] += f1 + f3;
                cr0[j] += r0 + r2;  cr1[j] += r1 + r3;
            }
            lsum += r0 * f0 + r1 * f1 + r2 * f2 + r3 * f3;
        }
    }
    #pragma unroll
    for (int off = 1; off < 4; off <<= 1) {
        #pragma unroll
        for (int i = 0; i < 2; i++) {
            rf[i][0] += __shfl_xor_sync(0xffffffffu, rf[i][0], off);
            rf[i][1] += __shfl_xor_sync(0xffffffffu, rf[i][1], off);
            rr[i][0] += __shfl_xor_sync(0xffffffffu, rr[i][0], off);
            rr[i][1] += __shfl_xor_sync(0xffffffffu, rr[i][1], off);
        }
    }
    if (t == 0) {
        #pragma unroll
        for (int i = 0; i < 2; i++) {
            int r0i = wm * 32 + i * 16 + g;
            atomicAdd(&red_f[r0i],     rf[i][0]);
            atomicAdd(&red_f[r0i + 8], rf[i][1]);
            atomicAdd(&red_r[r0i],     rr[i][0]);
            atomicAdd(&red_r[r0i + 8], rr[i][1]);
        }
    }
    if (SYM) {
        #pragma unroll
        for (int off = 4; off < 32; off <<= 1) {
            #pragma unroll
            for (int j = 0; j < 4; j++) {
                cf0[j] += __shfl_xor_sync(0xffffffffu, cf0[j], off);
                cf1[j] += __shfl_xor_sync(0xffffffffu, cf1[j], off);
                cr0[j] += __shfl_xor_sync(0xffffffffu, cr0[j], off);
                cr1[j] += __shfl_xor_sync(0xffffffffu, cr1[j], off);
            }
        }
        if (g == 0) {
            #pragma unroll
            for (int j = 0; j < 4; j++) {
                int c0i = wn * 32 + j * 8 + 2 * t;
                atomicAdd(&red_cf[c0i],     cf0[j]);
                atomicAdd(&red_cf[c0i + 1], cf1[j]);
                atomicAdd(&red_cr[c0i],     cr0[j]);
                atomicAdd(&red_cr[c0i + 1], cr1[j]);
            }
        }
    }
    #pragma unroll
    for (int off = 16; off; off >>= 1) lsum += __shfl_xor_sync(0xffffffffu, lsum, off);
    if (lane == 0) red_d[wid] = (double)lsum;
    __syncthreads();

    if (tid == 0) {
        double s = 0.0;
        #pragma unroll
        for (int w = 0; w < 16; w++) s += red_d[w];
        atomicAdd(&g_scal[slot], SYM ? 2.0 * s : s);
    }
    if (tid < 128) {
        int gi = slot * NB * NP + b * NP + p0 + tid;
        atomicAdd(&g_rowfd[gi], red_f[tid]);
        atomicAdd(&g_rowrc[gi], red_r[tid]);
        if (SYM) {
            int gj = slot * NB * NP + b * NP + q0 + tid;
            atomicAdd(&g_rowfd[gj], red_cf[tid]);
            atomicAdd(&g_rowrc[gj], red_cr[tid]);
        }
    }
}

__device__ const int8_t PAIR_P[36] = {0,0,0,0,0,0,0, 1,1,1,1,1,1, 2,2,2,2,2, 3,3,3,3, 4,4,4, 5,5, 6, 0,1,2,3,4,5,6,7};
__device__ const int8_t PAIR_Q[36] = {1,2,3,4,5,6,7, 2,3,4,5,6,7, 3,4,5,6,7, 4,5,6,7, 5,6,7, 6,7, 7, 0,1,2,3,4,5,6,7};

__global__ void __launch_bounds__(512, 1) corr_all_kernel()
{
    int x = blockIdx.x;
    if (x < 576) {
        int pair = x % 36;
        int b    = x / 36;
        int p0 = (int)PAIR_P[pair] * 128;
        int q0 = (int)PAIR_Q[pair] * 128;
        const uint8_t* Af = g_F1 + (size_t)(b * NP + p0) * CF;
        const __half*  Ac = g_C1 + (size_t)(b * NP + p0) * CC;
        const uint8_t* Bf = g_F1 + (size_t)(b * NP + q0) * CF;
        const __half*  Bc = g_C1 + (size_t)(b * NP + q0) * CC;
        if (pair < 28) corr_body<true >(0, b, p0, q0, Af, Ac, Bf, Bc);
        else           corr_body<false>(0, b, p0, q0, Af, Ac, Bf, Bc);
    } else {
        int j  = x - 576;
        int q0 = (j & 7) * 128;
        int p0 = ((j >> 3) & 7) * 128;
        int z  = j >> 6;
        int slot = 1 + (z >> 4);
        int b    = z & 15;
        const uint8_t* Bf;
        const __half*  Bc;
        switch (slot) {
            case 1:  Bf = g_F2p; Bc = g_C2p; break;
            case 2:  Bf = g_Fn0; Bc = g_Cn0; break;
            default: Bf = g_Fn1; Bc = g_Cn1; break;
        }
        corr_body<false>(slot, b, p0, q0,
                         g_F1 + (size_t)(b * NP + p0) * CF,
                         g_C1 + (size_t)(b * NP + p0) * CC,
                         Bf   + (size_t)(b * NP + q0) * CF,
                         Bc   + (size_t)(b * NP + q0) * CC);
    }
}

// ======================= parallel reduce + tiny finalize =======================
__global__ void __launch_bounds__(256) reduce_kernel()
{
    int blk  = blockIdx.x;
    int slot = blk >> 6;
    int tid  = threadIdx.x;
    int i = (blk & 63) * 256 + tid;

    float f = g_rowfd[slot * NB * NP + i];
    float r = g_rowrc[slot * NB * NP + i];
    double tf = (double)f, tr = (double)r, cx = (double)f * (double)r;

    #pragma unroll
    for (int off = 16; off; off >>= 1) {
        tf += __shfl_xor_sync(0xffffffffu, tf, off);
        tr += __shfl_xor_sync(0xffffffffu, tr, off);
        cx += __shfl_xor_sync(0xffffffffu, cx, off);
    }
    __shared__ double sred[3][8];
    if ((tid & 31) == 0) { sred[0][tid >> 5] = tf; sred[1][tid >> 5] = tr; sred[2][tid >> 5] = cx; }
    __syncthreads();
    if (tid < 8) {
        double a = sred[0][tid], b = sred[1][tid], c = sred[2][tid];
        #pragma unroll
        for (int off = 4; off; off >>= 1) {
            a += __shfl_xor_sync(0xffu, a, off);
            b += __shfl_xor_sync(0xffu, b, off);
            c += __shfl_xor_sync(0xffu, c, off);
        }
        if (tid == 0) {
            atomicAdd(&g_acc[slot][0], a);
            atomicAdd(&g_acc[slot][1], b);
            atomicAdd(&g_acc[slot][2], c);
        }
    }
}

__global__ void final_kernel(float* out)
{
    const double BPQ = (double)NB * (double)NP * (double)NP;
    const double Q   = (double)NP;
    const double shifts[4] = {0.18, 0.12, 0.46, 0.46};
    double loss[4];
    #pragma unroll
    for (int s = 0; s < 4; s++) {
        double tf = g_acc[s][0], tr = g_acc[s][1], cx = g_acc[s][2];
        double A  = g_scal[s];
        double gm = tf / BPQ;
        loss[s] = (-A + cx / Q) / BPQ - (gm - shifts[s]) * (tr / BPQ);
    }
    out[0] = (float)loss[0];
    out[1] = (float)loss[1];
    out[2] = (float)(0.5 * (loss[2] + loss[3]));
}

// ======================= launch =======================
extern "C" void kernel_launch(void* const* d_in, const int* in_sizes, int n_in,
                              void* d_out, int out_size)
{
    const float* orig_feats     = (const float*)d_in[0];
    const float* orig_feats_pos = (const float*)d_in[1];
    const float* orig_code      = (const float*)d_in[4];
    const float* orig_code_pos  = (const float*)d_in[5];
    const float* coords1        = (const float*)d_in[8];
    const float* coords2        = (const float*)d_in[9];
    const int*   perms          = (const int*)d_in[10];
    float* out = (float*)d_out;

    cudaFuncSetAttribute(corr_all_kernel, cudaFuncAttributeMaxDynamicSharedMemorySize, SMEM_BYTES);

    dim3 tb(32, 8);
    transpose_all_kernel<<<dim3(4800, 4), tb>>>(orig_feats, orig_feats_pos,
                                                orig_code, orig_code_pos);

    sample_all_kernel<<<dim3(NB * NP, 4), 160>>>(coords1, coords2, perms);

    corr_all_kernel<<<3648, 512, SMEM_BYTES>>>();

    reduce_kernel<<<256, 256>>>();
    final_kernel<<<1, 1>>>(out);
}